// round 9
// baseline (speedup 1.0000x reference)
#include <cuda_runtime.h>
#include <math.h>

#define G 8192
#define S 64
#define D 128
#define H 256
#define EPS 0.01f

// Output layout: rep [G*D] | mixture [G*8] | scale [G] | alpha [G] | beta [G]
#define O_REP   0
#define O_MIX   (G * D)
#define O_SCALE (O_MIX + G * 8)
#define O_ALPHA (O_SCALE + G)
#define O_BETA  (O_ALPHA + G)

#define TILE 8                   // groups per tile
#define NTILES (G / TILE)        // 1024
#define TPP 2                    // tiles per producer block
#define PROD_BLOCKS (NTILES / TPP)   // 512

// Cross-block ready flags. Zero at load; each consumer resets its flag after
// consuming, so every run (correctness + every graph replay) starts from 0.
__device__ int g_flags[NTILES];

__device__ __forceinline__ float softplus_f(float v) {
    return fmaxf(v, 0.f) + log1pf(expf(-fabsf(v)));
}

// ---------------------------------------------------------------------------
// One launch, two roles.
//   bid <  512 : stats for tiles {bid, bid+512}  (publishes each on finish)
//   bid >= 512 : MLP for tile (bid-512), spin-wait on producer flag
// Producers occupy the lowest bids -> all resident before any consumer that
// waits on them; staggered publication overlaps MLP with the DRAM stream.
// ---------------------------------------------------------------------------
__global__ __launch_bounds__(256) void fused_kernel(
    const float* __restrict__ x, const float* __restrict__ y,
    const float* __restrict__ ax, const float* __restrict__ ay,
    const float* __restrict__ W1, const float* __restrict__ b1,
    const float* __restrict__ W2, const float* __restrict__ b2,
    float* __restrict__ out)
{
    __shared__ float sA[TILE * D];     // 4 KB
    __shared__ float sH[TILE * H];     // 8 KB
    __shared__ float sW2[H * 10];      // 10 KB

    const int t = threadIdx.x;
    const int bid = blockIdx.x;
    const int warp = t >> 5;
    const int lane = t & 31;

    if (bid < PROD_BLOCKS) {
        // ================= producer role: TPP tiles =================
#pragma unroll 1
        for (int it = 0; it < TPP; ++it) {
            const int tile = bid + it * PROD_BLOCKS;
            const int g = tile * TILE + warp;

            const float4* xg = reinterpret_cast<const float4*>(x + (size_t)g * S * D) + lane;
            const float4  a4 = reinterpret_cast<const float4*>(ax + (size_t)g * D)[lane];
            const float   ayv = ay[g];
            const float*  yg = y + (size_t)g * S;

            float sx0 = 0.f, sx1 = 0.f, sx2 = 0.f, sx3 = 0.f;
            float sp0 = 0.f, sp1 = 0.f, sp2 = 0.f, sp3 = 0.f;
            float sxx = 0.f, sy = 0.f;

#pragma unroll 4
            for (int s = 0; s < S; ++s) {
                float4 xv = xg[s * 32];
                float  yv = __ldg(yg + s);
                float xr0 = xv.x - a4.x;
                float xr1 = xv.y - a4.y;
                float xr2 = xv.z - a4.z;
                float xr3 = xv.w - a4.w;
                float yr  = yv - ayv;
                sx0 += xr0; sx1 += xr1; sx2 += xr2; sx3 += xr3;
                sp0 += xr0 * yr; sp1 += xr1 * yr; sp2 += xr2 * yr; sp3 += xr3 * yr;
                sxx += xr0 * xr0 + xr1 * xr1 + xr2 * xr2 + xr3 * xr3;
                sy  += yr;
            }

            float tot = sx0 + sx1 + sx2 + sx3;
            float sxxT = sxx;
#pragma unroll
            for (int o = 16; o > 0; o >>= 1) {
                tot  += __shfl_xor_sync(0xffffffffu, tot,  o);
                sxxT += __shfl_xor_sync(0xffffffffu, sxxT, o);
            }

            const float nD = (float)(S * D);
            const float var = (sxxT - tot * tot / nD) / (nD - 1.f);
            const float inv = 1.f / var;
            const float invn  = 1.f / (float)S;
            const float invn1 = 1.f / (float)(S - 1);

            float4 r;
            r.x = (sp0 - sx0 * sy * invn) * invn1 * inv;
            r.y = (sp1 - sx1 * sy * invn) * invn1 * inv;
            r.z = (sp2 - sx2 * sy * invn) * invn1 * inv;
            r.w = (sp3 - sx3 * sy * invn) * invn1 * inv;
            reinterpret_cast<float4*>(out + O_REP + (size_t)g * D)[lane] = r;

            __syncthreads();
            __threadfence();
            if (t == 0) atomicExch(&g_flags[tile], 1);
        }
        return;
    }

    // ================= consumer role =================
    const int m = bid - PROD_BLOCKS;      // tile index; groups 8m..8m+7
    const float* rep = out + O_REP;

    // independent prefetch while waiting
    for (int i = t; i < H * 10; i += 256) sW2[i] = W2[i];

    if (t == 0) {
        while (atomicAdd(&g_flags[m], 0) == 0) __nanosleep(64);
        g_flags[m] = 0;                   // reset for next graph replay
    }
    __syncthreads();
    __threadfence();

    // load A tile (8 rows x 128) : 256 float4, one per thread
    reinterpret_cast<float4*>(sA)[t] =
        reinterpret_cast<const float4*>(rep + (size_t)m * TILE * D)[t];
    __syncthreads();

    // ---- GEMM1 + tanh: thread = rows {rr, rr+1} x cols [c0, c0+4) ----
    {
        const int rr = (t >> 6) * 2;
        const int c0 = (t & 63) * 4;
        const float* A0 = sA + rr * D;
        const float* A1 = A0 + D;
        const float4* W1v = reinterpret_cast<const float4*>(W1) + (c0 >> 2);

        float4 acc0 = {0.f, 0.f, 0.f, 0.f};
        float4 acc1 = {0.f, 0.f, 0.f, 0.f};
#pragma unroll 8
        for (int k = 0; k < D; ++k) {
            float4 w = W1v[k * (H / 4)];
            float a0 = A0[k];
            float a1 = A1[k];
            acc0.x += a0 * w.x; acc0.y += a0 * w.y;
            acc0.z += a0 * w.z; acc0.w += a0 * w.w;
            acc1.x += a1 * w.x; acc1.y += a1 * w.y;
            acc1.z += a1 * w.z; acc1.w += a1 * w.w;
        }
        float4 bb = reinterpret_cast<const float4*>(b1)[c0 >> 2];
        float4 h0, h1;
        h0.x = tanhf(acc0.x + bb.x); h0.y = tanhf(acc0.y + bb.y);
        h0.z = tanhf(acc0.z + bb.z); h0.w = tanhf(acc0.w + bb.w);
        h1.x = tanhf(acc1.x + bb.x); h1.y = tanhf(acc1.y + bb.y);
        h1.z = tanhf(acc1.z + bb.z); h1.w = tanhf(acc1.w + bb.w);
        reinterpret_cast<float4*>(sH + rr * H + c0)[0] = h0;
        reinterpret_cast<float4*>(sH + (rr + 1) * H + c0)[0] = h1;
    }
    __syncthreads();

    // ---- GEMM2 + epilogue: warp = group ----
    {
        float p[10];
#pragma unroll
        for (int k = 0; k < 10; ++k) p[k] = 0.f;

        const float* hrow = sH + warp * H;
#pragma unroll
        for (int j = 0; j < 8; ++j) {
            float hv = hrow[lane + 32 * j];
            const float* w2r = sW2 + (lane + 32 * j) * 10;
#pragma unroll
            for (int k = 0; k < 10; ++k) p[k] += hv * w2r[k];
        }
#pragma unroll
        for (int k = 0; k < 10; ++k) {
#pragma unroll
            for (int o = 16; o > 0; o >>= 1)
                p[k] += __shfl_xor_sync(0xffffffffu, p[k], o);
        }

        if (lane == 0) {
            const int g = m * TILE + warp;
            float o0 = p[0] + __ldg(b2 + 0);
            float o1 = p[1] + __ldg(b2 + 1);
            float alpha = softplus_f(o0) * (1.f - EPS) + EPS;
            float beta  = softplus_f(o1) * (1.f - EPS) + EPS;

            float lg[8];
            float mx = -3.4e38f;
#pragma unroll
            for (int k = 0; k < 8; ++k) {
                lg[k] = p[2 + k] + __ldg(b2 + 2 + k);
                mx = fmaxf(mx, lg[k]);
            }
            float se = 0.f;
#pragma unroll
            for (int k = 0; k < 8; ++k) { lg[k] = expf(lg[k] - mx); se += lg[k]; }
            float inv_se = 1.f / se;
#pragma unroll
            for (int k = 0; k < 8; ++k) out[O_MIX + (size_t)g * 8 + k] = lg[k] * inv_se;

            out[O_SCALE + g] = sqrtf(beta / alpha);
            out[O_ALPHA + g] = alpha;
            out[O_BETA  + g] = beta;
        }
    }
}

// ---------------------------------------------------------------------------
extern "C" void kernel_launch(void* const* d_in, const int* in_sizes, int n_in,
                              void* d_out, int out_size)
{
    (void)in_sizes; (void)n_in; (void)out_size;
    // inputs: 0=index(int32), 1=x, 2=y, 3=anchor_x, 4=anchor_y, 5=W1, 6=b1, 7=W2, 8=b2
    const float* x  = (const float*)d_in[1];
    const float* y  = (const float*)d_in[2];
    const float* ax = (const float*)d_in[3];
    const float* ay = (const float*)d_in[4];
    const float* W1 = (const float*)d_in[5];
    const float* b1 = (const float*)d_in[6];
    const float* W2 = (const float*)d_in[7];
    const float* b2 = (const float*)d_in[8];
    float* out = (float*)d_out;

    fused_kernel<<<PROD_BLOCKS + NTILES, 256>>>(x, y, ax, ay, W1, b1, W2, b2, out);
}

// round 12
// speedup vs baseline: 1.4354x; 1.4354x over previous
#include <cuda_runtime.h>
#include <math.h>

#define G 8192
#define S 64
#define D 128
#define H 256
#define EPS 0.01f

// Output layout: rep [G*D] | mixture [G*8] | scale [G] | alpha [G] | beta [G]
#define O_REP   0
#define O_MIX   (G * D)
#define O_SCALE (O_MIX + G * 8)
#define O_ALPHA (O_SCALE + G)
#define O_BETA  (O_ALPHA + G)

#define TILE 8                   // groups per producer tile
#define NTILES (G / TILE)        // 1024 producer blocks
#define CGROUPS 16               // groups per consumer block
#define NCONS (G / CGROUPS)      // 512 consumer blocks

// Cross-block ready flags. Zero at load; each consumer resets the flags it
// consumed, so every run (correctness + every graph replay) starts from 0.
__device__ int g_flags[NTILES];

__device__ __forceinline__ float softplus_f(float v) {
    return fmaxf(v, 0.f) + log1pf(expf(-fabsf(v)));
}

__device__ __forceinline__ unsigned long long pack2(float lo, float hi) {
    unsigned long long r;
    asm("mov.b64 %0, {%1, %2};" : "=l"(r) : "f"(lo), "f"(hi));
    return r;
}
__device__ __forceinline__ void unpack2(unsigned long long v, float& lo, float& hi) {
    asm("mov.b64 {%0, %1}, %2;" : "=f"(lo), "=f"(hi) : "l"(v));
}
__device__ __forceinline__ void fma2(unsigned long long& d,
                                     unsigned long long a, unsigned long long b) {
    asm("fma.rn.f32x2 %0, %1, %2, %0;" : "+l"(d) : "l"(a), "l"(b));
}

// ---------------------------------------------------------------------------
// One launch, two roles (R8 schedule: ALL producers at low bids, consumers
// strictly behind them — consumers only run as producers retire).
//   bid <  1024 : stats for tile bid (groups 8*bid..8*bid+7)   [R8 body]
//   bid >= 1024 : MLP for groups [16m, 16m+16), m = bid-1024; waits on
//                 tiles {2m, 2m+1}. f32x2 packed FMA in GEMM1.
// ---------------------------------------------------------------------------
__global__ __launch_bounds__(256) void fused_kernel(
    const float* __restrict__ x, const float* __restrict__ y,
    const float* __restrict__ ax, const float* __restrict__ ay,
    const float* __restrict__ W1, const float* __restrict__ b1,
    const float* __restrict__ W2, const float* __restrict__ b2,
    float* __restrict__ out)
{
    __shared__ float sA[CGROUPS * D];   // 8 KB
    __shared__ float sH[CGROUPS * H];   // 16 KB
    __shared__ float sW2[H * 10];       // 10 KB

    const int t = threadIdx.x;
    const int bid = blockIdx.x;
    const int warp = t >> 5;
    const int lane = t & 31;

    if (bid < NTILES) {
        // ================= producer role (exact R8 body) =================
        const int g = bid * TILE + warp;

        const float4* xg = reinterpret_cast<const float4*>(x + (size_t)g * S * D) + lane;
        const float4  a4 = reinterpret_cast<const float4*>(ax + (size_t)g * D)[lane];
        const float   ayv = ay[g];
        const float*  yg = y + (size_t)g * S;

        float sx0 = 0.f, sx1 = 0.f, sx2 = 0.f, sx3 = 0.f;
        float sp0 = 0.f, sp1 = 0.f, sp2 = 0.f, sp3 = 0.f;
        float sxx = 0.f, sy = 0.f;

#pragma unroll 4
        for (int s = 0; s < S; ++s) {
            float4 xv = xg[s * 32];
            float  yv = __ldg(yg + s);
            float xr0 = xv.x - a4.x;
            float xr1 = xv.y - a4.y;
            float xr2 = xv.z - a4.z;
            float xr3 = xv.w - a4.w;
            float yr  = yv - ayv;
            sx0 += xr0; sx1 += xr1; sx2 += xr2; sx3 += xr3;
            sp0 += xr0 * yr; sp1 += xr1 * yr; sp2 += xr2 * yr; sp3 += xr3 * yr;
            sxx += xr0 * xr0 + xr1 * xr1 + xr2 * xr2 + xr3 * xr3;
            sy  += yr;
        }

        float tot = sx0 + sx1 + sx2 + sx3;
        float sxxT = sxx;
#pragma unroll
        for (int o = 16; o > 0; o >>= 1) {
            tot  += __shfl_xor_sync(0xffffffffu, tot,  o);
            sxxT += __shfl_xor_sync(0xffffffffu, sxxT, o);
        }

        const float nD = (float)(S * D);
        const float var = (sxxT - tot * tot / nD) / (nD - 1.f);
        const float inv = 1.f / var;
        const float invn  = 1.f / (float)S;
        const float invn1 = 1.f / (float)(S - 1);

        float4 r;
        r.x = (sp0 - sx0 * sy * invn) * invn1 * inv;
        r.y = (sp1 - sx1 * sy * invn) * invn1 * inv;
        r.z = (sp2 - sx2 * sy * invn) * invn1 * inv;
        r.w = (sp3 - sx3 * sy * invn) * invn1 * inv;
        reinterpret_cast<float4*>(out + O_REP + (size_t)g * D)[lane] = r;

        __syncthreads();
        __threadfence();
        if (t == 0) atomicExch(&g_flags[bid], 1);
        return;
    }

    // ================= consumer role =================
    const int m = bid - NTILES;           // 0..511; groups [16m, 16m+16)
    const float* rep = out + O_REP;

    // independent prefetch while waiting
    for (int i = t; i < H * 10; i += 256) sW2[i] = W2[i];

    if (t == 0) {
        while (atomicAdd(&g_flags[2 * m], 0) == 0) __nanosleep(64);
        while (atomicAdd(&g_flags[2 * m + 1], 0) == 0) __nanosleep(64);
        g_flags[2 * m] = 0;               // reset for next graph replay
        g_flags[2 * m + 1] = 0;
    }
    __syncthreads();
    __threadfence();

    // load A tile (16 rows x 128) : 512 float4
    {
        const float4* src = reinterpret_cast<const float4*>(rep + (size_t)m * CGROUPS * D);
        float4* dst = reinterpret_cast<float4*>(sA);
        dst[t] = src[t];
        dst[t + 256] = src[t + 256];
    }
    __syncthreads();

    // ---- GEMM1 + tanh: thread = rows [4*rg, 4*rg+4) x cols [c0, c0+4) ----
    {
        const int rg = t >> 6;            // 0..3
        const int c0 = (t & 63) * 4;
        const float* Ab = sA + rg * 4 * D;
        const float4* W1v = reinterpret_cast<const float4*>(W1) + (c0 >> 2);

        unsigned long long acc[4][2];
#pragma unroll
        for (int r = 0; r < 4; ++r) { acc[r][0] = pack2(0.f, 0.f); acc[r][1] = pack2(0.f, 0.f); }

#pragma unroll 8
        for (int k = 0; k < D; ++k) {
            float4 w = W1v[k * (H / 4)];
            unsigned long long wp0 = pack2(w.x, w.y);
            unsigned long long wp1 = pack2(w.z, w.w);
#pragma unroll
            for (int r = 0; r < 4; ++r) {
                float a = Ab[r * D + k];
                unsigned long long ap = pack2(a, a);
                fma2(acc[r][0], ap, wp0);
                fma2(acc[r][1], ap, wp1);
            }
        }

        float4 bb = reinterpret_cast<const float4*>(b1)[c0 >> 2];
#pragma unroll
        for (int r = 0; r < 4; ++r) {
            float v0, v1, v2, v3;
            unpack2(acc[r][0], v0, v1);
            unpack2(acc[r][1], v2, v3);
            float4 h;
            h.x = tanhf(v0 + bb.x);
            h.y = tanhf(v1 + bb.y);
            h.z = tanhf(v2 + bb.z);
            h.w = tanhf(v3 + bb.w);
            *reinterpret_cast<float4*>(sH + (rg * 4 + r) * H + c0) = h;
        }
    }
    __syncthreads();

    // ---- GEMM2 + epilogue: warp handles groups {2*warp, 2*warp+1} ----
#pragma unroll
    for (int i = 0; i < 2; ++i) {
        const int row = warp * 2 + i;
        const float* hrow = sH + row * H;

        float p[10];
#pragma unroll
        for (int k = 0; k < 10; ++k) p[k] = 0.f;

#pragma unroll
        for (int j = 0; j < 8; ++j) {
            float hv = hrow[lane + 32 * j];
            const float* w2r = sW2 + (lane + 32 * j) * 10;
#pragma unroll
            for (int k = 0; k < 10; ++k) p[k] += hv * w2r[k];
        }
#pragma unroll
        for (int k = 0; k < 10; ++k) {
#pragma unroll
            for (int o = 16; o > 0; o >>= 1)
                p[k] += __shfl_xor_sync(0xffffffffu, p[k], o);
        }

        if (lane == 0) {
            const int g = m * CGROUPS + row;
            float o0 = p[0] + __ldg(b2 + 0);
            float o1 = p[1] + __ldg(b2 + 1);
            float alpha = softplus_f(o0) * (1.f - EPS) + EPS;
            float beta  = softplus_f(o1) * (1.f - EPS) + EPS;

            float lg[8];
            float mx = -3.4e38f;
#pragma unroll
            for (int k = 0; k < 8; ++k) {
                lg[k] = p[2 + k] + __ldg(b2 + 2 + k);
                mx = fmaxf(mx, lg[k]);
            }
            float se = 0.f;
#pragma unroll
            for (int k = 0; k < 8; ++k) { lg[k] = expf(lg[k] - mx); se += lg[k]; }
            float inv_se = 1.f / se;
#pragma unroll
            for (int k = 0; k < 8; ++k) out[O_MIX + (size_t)g * 8 + k] = lg[k] * inv_se;

            out[O_SCALE + g] = sqrtf(beta / alpha);
            out[O_ALPHA + g] = alpha;
            out[O_BETA  + g] = beta;
        }
    }
}

// ---------------------------------------------------------------------------
extern "C" void kernel_launch(void* const* d_in, const int* in_sizes, int n_in,
                              void* d_out, int out_size)
{
    (void)in_sizes; (void)n_in; (void)out_size;
    // inputs: 0=index(int32), 1=x, 2=y, 3=anchor_x, 4=anchor_y, 5=W1, 6=b1, 7=W2, 8=b2
    const float* x  = (const float*)d_in[1];
    const float* y  = (const float*)d_in[2];
    const float* ax = (const float*)d_in[3];
    const float* ay = (const float*)d_in[4];
    const float* W1 = (const float*)d_in[5];
    const float* b1 = (const float*)d_in[6];
    const float* W2 = (const float*)d_in[7];
    const float* b2 = (const float*)d_in[8];
    float* out = (float*)d_out;

    fused_kernel<<<NTILES + NCONS, 256>>>(x, y, ax, ay, W1, b1, W2, b2, out);
}